// round 6
// baseline (speedup 1.0000x reference)
#include <cuda_runtime.h>

#define B_  4
#define S_  2048
#define DM_ 1024
#define H_  16
#define DK_ 64
#define M_  (B_*S_)   // 8192 rows

// Scratch (allocation-free rule: __device__ globals)
__device__ float g_Qh[(size_t)B_*H_*S_*DK_];
__device__ float g_Kh[(size_t)B_*H_*S_*DK_];
__device__ float g_Vh[(size_t)B_*H_*S_*DK_];
__device__ float g_Ctx[(size_t)M_*DM_];
__device__ float g_invl[(size_t)B_*H_*S_];
__device__ unsigned g_mbits[(size_t)B_*S_*(S_/32)];   // packed mask bits

// ---------------------------------------------------------------------------
// helpers
// ---------------------------------------------------------------------------
__device__ __forceinline__ unsigned f2tf(float x) {
    unsigned u;
    asm("cvt.rna.tf32.f32 %0, %1;" : "=r"(u) : "f"(x));
    return u;
}
__device__ __forceinline__ void mma_tf32(float c[4],
                                         unsigned a0, unsigned a1, unsigned a2, unsigned a3,
                                         unsigned b0, unsigned b1) {
    asm("mma.sync.aligned.m16n8k8.row.col.f32.tf32.tf32.f32 "
        "{%0,%1,%2,%3},{%4,%5,%6,%7},{%8,%9},{%0,%1,%2,%3};"
        : "+f"(c[0]), "+f"(c[1]), "+f"(c[2]), "+f"(c[3])
        : "r"(a0), "r"(a1), "r"(a2), "r"(a3), "r"(b0), "r"(b1));
}
__device__ __forceinline__ unsigned sm_u32(const void* p) {
    return (unsigned)__cvta_generic_to_shared(p);
}
__device__ __forceinline__ void ldsm4(unsigned r[4], unsigned addr) {
    asm volatile("ldmatrix.sync.aligned.m8n8.x4.shared.b16 {%0,%1,%2,%3}, [%4];"
        : "=r"(r[0]), "=r"(r[1]), "=r"(r[2]), "=r"(r[3]) : "r"(addr));
}

// ---------------------------------------------------------------------------
// Pack mask into bits: g_mbits[b][row][w] bit j = (mask[b][row][32w+j] != 0)
// ---------------------------------------------------------------------------
__global__ __launch_bounds__(256) void pack_mask(const int* __restrict__ mask)
{
    const int lane = threadIdx.x & 31;
    const int gw = blockIdx.x * 8 + (threadIdx.x >> 5);   // global word index
    int m = mask[(size_t)gw * 32 + lane];
    unsigned bits = __ballot_sync(0xffffffffu, m != 0);
    if (lane == 0) g_mbits[gw] = bits;
}

// ---------------------------------------------------------------------------
// Projection GEMM (tf32 mma + ldmatrix + double-buffered smem).
// Y = X @ W^T (+bias). 128x128 tile, BK=32, 8 warps 2(m)x4(n); warp 64m x 32n.
// One __syncthreads per BK iter; LDG(i+1) issues before mma(i).
// dyn smem: [X0 4608 | W0 4608 | X1 4608 | W1 4608] words = 73728 B
// ---------------------------------------------------------------------------
#define XSTR 36
#define PBUF 9216            // words per (X,W) buffer pair
__global__ __launch_bounds__(256) void proj_mma(const float* __restrict__ X,
                                                const float* __restrict__ W,
                                                const float* __restrict__ bias,
                                                float* __restrict__ Y,
                                                int headsMode)
{
    extern __shared__ unsigned psm[];
    unsigned* Xs = psm;             // + buf*PBUF
    unsigned* Ws = psm + 4608;      // + buf*PBUF
    const int tid = threadIdx.x;
    const int lane = tid & 31, wid = tid >> 5;
    const int wm = wid >> 2, wn = wid & 3;
    const int gr = lane >> 2, tg = lane & 3;
    const int m0 = blockIdx.x * 128, n0 = blockIdx.y * 128;

    const int arow = lane & 15;
    const int acol = ((lane >> 4) & 1) * 4;
    const int brow = ((lane >> 4) & 1) * 8 + (lane & 7);
    const int bcol = ((lane >> 3) & 1) * 4;
    const unsigned abase = sm_u32(Xs + (wm*64 + arow)*XSTR + acol);
    const unsigned bbase = sm_u32(Ws + (wn*32 + brow)*XSTR + bcol);

    const int lr = tid >> 1;          // 0..127 (row)
    const int lh = (tid & 1) * 16;    // k-half
    const int sts = lr * XSTR + lh;   // word offset within buffer

    float c[4][4][4];
    #pragma unroll
    for (int mi = 0; mi < 4; mi++)
        #pragma unroll
        for (int ni = 0; ni < 4; ni++)
            #pragma unroll
            for (int r = 0; r < 4; r++) c[mi][ni][r] = 0.f;

    const float* Xp = X + (size_t)(m0 + lr) * DM_ + lh;
    const float* Wp = W + (size_t)(n0 + lr) * DM_ + lh;

    float4 px[4], pw[4];
    #pragma unroll
    for (int j = 0; j < 4; j++) { px[j] = *(const float4*)(Xp + 4*j); pw[j] = *(const float4*)(Wp + 4*j); }
    #pragma unroll
    for (int j = 0; j < 4; j++) {
        *(uint4*)&Xs[sts + 4*j] = make_uint4(f2tf(px[j].x), f2tf(px[j].y), f2tf(px[j].z), f2tf(px[j].w));
        *(uint4*)&Ws[sts + 4*j] = make_uint4(f2tf(pw[j].x), f2tf(pw[j].y), f2tf(pw[j].z), f2tf(pw[j].w));
    }
    __syncthreads();

    #pragma unroll 1
    for (int it = 0; it < 32; it++) {
        const int cur = it & 1;
        const unsigned bufOff = (unsigned)cur * (PBUF * 4u);
        const bool hasNext = (it + 1 < 32);

        if (hasNext) {
            const float* Xn = Xp + (it + 1) * 32;
            const float* Wn = Wp + (it + 1) * 32;
            #pragma unroll
            for (int j = 0; j < 4; j++) { px[j] = *(const float4*)(Xn + 4*j); pw[j] = *(const float4*)(Wn + 4*j); }
        }

        #pragma unroll
        for (int kc = 0; kc < 4; kc++) {
            unsigned a[4][4], bb[4][2];
            #pragma unroll
            for (int mi = 0; mi < 4; mi++)
                ldsm4(a[mi], abase + bufOff + (unsigned)(mi*16*XSTR + kc*8) * 4u);
            #pragma unroll
            for (int np = 0; np < 2; np++) {
                unsigned t[4];
                ldsm4(t, bbase + bufOff + (unsigned)(np*16*XSTR + kc*8) * 4u);
                bb[2*np][0] = t[0]; bb[2*np][1] = t[1];
                bb[2*np+1][0] = t[2]; bb[2*np+1][1] = t[3];
            }
            #pragma unroll
            for (int mi = 0; mi < 4; mi++)
                #pragma unroll
                for (int ni = 0; ni < 4; ni++)
                    mma_tf32(c[mi][ni], a[mi][0], a[mi][1], a[mi][2], a[mi][3],
                             bb[ni][0], bb[ni][1]);
        }

        if (hasNext) {
            const int nb = (1 - cur) * PBUF;
            #pragma unroll
            for (int j = 0; j < 4; j++) {
                *(uint4*)&Xs[nb + sts + 4*j] =
                    make_uint4(f2tf(px[j].x), f2tf(px[j].y), f2tf(px[j].z), f2tf(px[j].w));
                *(uint4*)&Ws[nb + sts + 4*j] =
                    make_uint4(f2tf(pw[j].x), f2tf(pw[j].y), f2tf(pw[j].z), f2tf(pw[j].w));
            }
        }
        __syncthreads();
    }

    if (headsMode) {
        #pragma unroll
        for (int mi = 0; mi < 4; mi++) {
            int m = m0 + wm*64 + mi*16 + gr;
            int b = m >> 11, s = m & (S_ - 1);
            #pragma unroll
            for (int ni = 0; ni < 4; ni++) {
                int n = n0 + wn*32 + ni*8 + 2*tg;
                int h = n >> 6, dk = n & 63;
                size_t base = (((size_t)(b*H_ + h) * S_) + s) * DK_ + dk;
                *(float2*)&Y[base]         = make_float2(c[mi][ni][0], c[mi][ni][1]);
                *(float2*)&Y[base + 8*DK_] = make_float2(c[mi][ni][2], c[mi][ni][3]);
            }
        }
    } else {
        #pragma unroll
        for (int mi = 0; mi < 4; mi++) {
            int m = m0 + wm*64 + mi*16 + gr;
            #pragma unroll
            for (int ni = 0; ni < 4; ni++) {
                int n = n0 + wn*32 + ni*8 + 2*tg;
                float b0 = bias[n], b1 = bias[n+1];
                *(float2*)&Y[(size_t)m * DM_ + n] =
                    make_float2(c[mi][ni][0] + b0, c[mi][ni][1] + b1);
                *(float2*)&Y[(size_t)(m+8) * DM_ + n] =
                    make_float2(c[mi][ni][2] + b0, c[mi][ni][3] + b1);
            }
        }
    }
}

// ---------------------------------------------------------------------------
// Fused attention, 512 threads / 16 warps. CTA: 128 queries, 16 key-tiles.
// Scores: warps 4(m)x4(n), warp 32q x 32k, ldmatrix A/B. PV: warps 4(m)x4(n),
// warp 32q x 16d, A (P) via ldmatrix, B (V natural, stride 72) via scalar LDS.
// Attention output written AFTER PV from Ps as coalesced STG.128.
// smem words: Qs 128*68 | Ks 128*68 | Vs 128*72 | Ps 128*132 | rowSum 128
// ---------------------------------------------------------------------------
#define QSTR 68
#define VSTR 72
#define PSTR2 132
#define OFF_KS 8704
#define OFF_VS 17408
#define OFF_PS 26624
#define OFF_RS 43520
#define SM_WORDS 43648

__global__ __launch_bounds__(512) void attn_mma(float* __restrict__ attn)
{
    extern __shared__ unsigned smu[];
    unsigned* Qs = smu;
    unsigned* Ks = smu + OFF_KS;
    unsigned* Vs = smu + OFF_VS;   // natural [key][d], stride 72
    unsigned* Ps = smu + OFF_PS;
    float* rowSum = (float*)(smu + OFF_RS);

    const int tid = threadIdx.x;
    const int lane = tid & 31, wid = tid >> 5;
    const int wm = wid >> 2, wn = wid & 3;       // score map: 32q x 32k
    const int wm2 = wid & 3, wn2 = wid >> 2;     // PV map:    32q x 16d
    const int gr = lane >> 2, tg = lane & 3;
    const int qt = blockIdx.x, bh = blockIdx.y;
    const int b = bh >> 4, h = bh & 15;

    const int arow = lane & 15;
    const int acol = ((lane >> 4) & 1) * 4;
    const int brow = ((lane >> 4) & 1) * 8 + (lane & 7);
    const int bcol = ((lane >> 3) & 1) * 4;
    const unsigned qbase = sm_u32(Qs + (wm*32 + arow)*QSTR + acol);
    const unsigned kbase = sm_u32(Ks + (wn*32 + brow)*QSTR + bcol);
    const unsigned pbase = sm_u32(Ps + (wm2*32 + arow)*PSTR2 + acol);

    const float* Qb = g_Qh + ((size_t)bh * S_ + qt*128) * DK_;
    const float* Kb = g_Kh + (size_t)bh * S_ * DK_;
    const float* Vb = g_Vh + (size_t)bh * S_ * DK_;
    const unsigned* mbp = g_mbits + ((size_t)b * S_ + qt*128) * (S_/32);
    float* ab = attn + (size_t)bh * S_ * S_ + (size_t)qt * 128 * S_;

    if (tid < 128) rowSum[tid] = 0.f;

    const int lr = tid >> 2;            // 0..127
    const int seg = (tid & 3) * 16;     // d quarter
    { // Q load: scale by 1/sqrt(64), tf32 round
        const float* qp = Qb + (size_t)lr * DK_ + seg;
        #pragma unroll
        for (int j = 0; j < 4; j++) {
            float4 v = *(const float4*)(qp + 4*j);
            *(uint4*)&Qs[lr*QSTR + seg + 4*j] =
                make_uint4(f2tf(v.x*0.125f), f2tf(v.y*0.125f),
                           f2tf(v.z*0.125f), f2tf(v.w*0.125f));
        }
    }

    float lacc[4];
    #pragma unroll
    for (int i = 0; i < 4; i++) lacc[i] = 0.f;
    float cacc[2][2][4];
    #pragma unroll
    for (int mi = 0; mi < 2; mi++)
        #pragma unroll
        for (int f = 0; f < 2; f++)
            #pragma unroll
            for (int r = 0; r < 4; r++) cacc[mi][f][r] = 0.f;

    for (int kt = 0; kt < 16; kt++) {
        __syncthreads();   // prev PV + attn-write done with Vs/Ps; first iter: Qs/rowSum ready
        // mask word prefetch (bits for this warp's 32-key window)
        unsigned mw[2][2];
        #pragma unroll
        for (int mi = 0; mi < 2; mi++) {
            const int r0 = wm*32 + mi*16 + gr;
            mw[mi][0] = mbp[(size_t)r0      * (S_/32) + kt*4 + wn];
            mw[mi][1] = mbp[(size_t)(r0+8)  * (S_/32) + kt*4 + wn];
        }
        { // K (row-major, stride 68) and V (natural, stride 72), tf32 round
            const float* kp = Kb + (size_t)(kt*128 + lr) * DK_ + seg;
            const float* vp = Vb + (size_t)(kt*128 + lr) * DK_ + seg;
            #pragma unroll
            for (int j = 0; j < 4; j++) {
                float4 kv = *(const float4*)(kp + 4*j);
                *(uint4*)&Ks[lr*QSTR + seg + 4*j] =
                    make_uint4(f2tf(kv.x), f2tf(kv.y), f2tf(kv.z), f2tf(kv.w));
                float4 vv = *(const float4*)(vp + 4*j);
                *(uint4*)&Vs[lr*VSTR + seg + 4*j] =
                    make_uint4(f2tf(vv.x), f2tf(vv.y), f2tf(vv.z), f2tf(vv.w));
            }
        }
        __syncthreads();

        // ---- scores: warp tile 32q x 32k, k-dim = 64 ----
        float sc[2][4][4];
        #pragma unroll
        for (int mi = 0; mi < 2; mi++)
            #pragma unroll
            for (int ni = 0; ni < 4; ni++)
                #pragma unroll
                for (int r = 0; r < 4; r++) sc[mi][ni][r] = 0.f;

        #pragma unroll
        for (int kc = 0; kc < 8; kc++) {
            unsigned a[2][4], bb[4][2];
            #pragma unroll
            for (int mi = 0; mi < 2; mi++)
                ldsm4(a[mi], qbase + (unsigned)(mi*16*QSTR + kc*8) * 4u);
            #pragma unroll
            for (int np = 0; np < 2; np++) {
                unsigned t[4];
                ldsm4(t, kbase + (unsigned)(np*16*QSTR + kc*8) * 4u);
                bb[2*np][0] = t[0]; bb[2*np][1] = t[1];
                bb[2*np+1][0] = t[2]; bb[2*np+1][1] = t[3];
            }
            #pragma unroll
            for (int mi = 0; mi < 2; mi++)
                #pragma unroll
                for (int ni = 0; ni < 4; ni++)
                    mma_tf32(sc[mi][ni], a[mi][0], a[mi][1], a[mi][2], a[mi][3],
                             bb[ni][0], bb[ni][1]);
        }

        // ---- mask(bits) + exp; unnormalized probs -> Ps (tf32) ----
        #pragma unroll
        for (int mi = 0; mi < 2; mi++) {
            const int r0 = wm*32 + mi*16 + gr;
            #pragma unroll
            for (int ni = 0; ni < 4; ni++) {
                const int ck = wn*32 + ni*8 + 2*tg;
                const int bit = ni*8 + 2*tg;
                float p00 = (mw[mi][0] >> bit     & 1u) ? __expf(sc[mi][ni][0]) : 0.f;
                float p01 = (mw[mi][0] >> (bit+1) & 1u) ? __expf(sc[mi][ni][1]) : 0.f;
                float p10 = (mw[mi][1] >> bit     & 1u) ? __expf(sc[mi][ni][2]) : 0.f;
                float p11 = (mw[mi][1] >> (bit+1) & 1u) ? __expf(sc[mi][ni][3]) : 0.f;
                lacc[mi*2]   += p00 + p01;
                lacc[mi*2+1] += p10 + p11;
                *(uint2*)&Ps[r0    *PSTR2 + ck] = make_uint2(f2tf(p00), f2tf(p01));
                *(uint2*)&Ps[(r0+8)*PSTR2 + ck] = make_uint2(f2tf(p10), f2tf(p11));
            }
        }
        __syncthreads();

        // ---- PV: warp tile 32q x 16d, k-dim = 128 keys ----
        // B frags via scalar LDS (conflict-free: bank = 8*tg + gr + const)
        #pragma unroll
        for (int kc = 0; kc < 16; kc++) {
            unsigned a2[2][4];
            ldsm4(a2[0], pbase + (unsigned)(kc*8) * 4u);
            ldsm4(a2[1], pbase + (unsigned)(16*PSTR2 + kc*8) * 4u);
            unsigned vb[2][2];
            #pragma unroll
            for (int f = 0; f < 2; f++) {
                const int d = wn2*16 + f*8 + gr;
                vb[f][0] = Vs[(kc*8 + tg    )*VSTR + d];
                vb[f][1] = Vs[(kc*8 + tg + 4)*VSTR + d];
            }
            #pragma unroll
            for (int mi = 0; mi < 2; mi++)
                #pragma unroll
                for (int f = 0; f < 2; f++)
                    mma_tf32(cacc[mi][f], a2[mi][0], a2[mi][1], a2[mi][2], a2[mi][3],
                             vb[f][0], vb[f][1]);
        }

        // ---- attention output: coalesced rows from Ps (tf32-rounded probs) ----
        #pragma unroll
        for (int i = 0; i < 8; i++) {
            const int row = wid*8 + i;
            float4 pv = *(float4*)&Ps[row*PSTR2 + 4*lane];
            *(float4*)&ab[(size_t)row * S_ + kt*128 + 4*lane] = pv;
        }
    }

    // ---- row sums: quad shuffle reduce + cross-warp atomic ----
    #pragma unroll
    for (int i = 0; i < 4; i++) {
        float v = lacc[i];
        v += __shfl_xor_sync(0xffffffffu, v, 1);
        v += __shfl_xor_sync(0xffffffffu, v, 2);
        lacc[i] = v;
    }
    if (tg == 0) {
        #pragma unroll
        for (int mi = 0; mi < 2; mi++) {
            atomicAdd(&rowSum[wm*32 + mi*16 + gr],     lacc[mi*2]);
            atomicAdd(&rowSum[wm*32 + mi*16 + gr + 8], lacc[mi*2+1]);
        }
    }
    __syncthreads();
    if (tid < 128)
        g_invl[(size_t)bh * S_ + qt*128 + tid] = 1.0f / rowSum[tid];

    // ---- context write (scaled by 1/l), permuted to [b][s][h*64+d] ----
    #pragma unroll
    for (int mi = 0; mi < 2; mi++) {
        const int r0 = wm2*32 + mi*16 + gr;
        const float s0 = 1.0f / rowSum[r0];
        const float s1 = 1.0f / rowSum[r0 + 8];
        #pragma unroll
        for (int f = 0; f < 2; f++) {
            const int d = wn2*16 + f*8 + 2*tg;
            size_t d0 = ((size_t)(b*S_ + qt*128 + r0    )) * DM_ + h*DK_ + d;
            size_t d1 = ((size_t)(b*S_ + qt*128 + r0 + 8)) * DM_ + h*DK_ + d;
            *(float2*)&g_Ctx[d0] = make_float2(cacc[mi][f][0]*s0, cacc[mi][f][1]*s0);
            *(float2*)&g_Ctx[d1] = make_float2(cacc[mi][f][2]*s1, cacc[mi][f][3]*s1);
        }
    }
}

// ---------------------------------------------------------------------------
// Normalize attention rows: attn[row][:] *= invl[row]
// ---------------------------------------------------------------------------
__global__ __launch_bounds__(256) void rescale(float* __restrict__ attn)
{
    const int row = blockIdx.x;
    const float s = g_invl[row];
    float4* p = (float4*)(attn + (size_t)row * S_);
    const int t = threadIdx.x;
    float4 v0 = p[t], v1 = p[t + 256];
    v0.x *= s; v0.y *= s; v0.z *= s; v0.w *= s;
    v1.x *= s; v1.y *= s; v1.z *= s; v1.w *= s;
    p[t] = v0; p[t + 256] = v1;
}

// ---------------------------------------------------------------------------
extern "C" void kernel_launch(void* const* d_in, const int* in_sizes, int n_in,
                              void* d_out, int out_size)
{
    const float* q    = (const float*)d_in[0];
    const float* k    = (const float*)d_in[1];
    const float* v    = (const float*)d_in[2];
    const int*   mask = (const int*)  d_in[3];
    const float* Wq   = (const float*)d_in[4];
    const float* Wk   = (const float*)d_in[5];
    const float* Wv   = (const float*)d_in[6];
    const float* Wo   = (const float*)d_in[7];
    const float* bo   = (const float*)d_in[8];

    float* out      = (float*)d_out;
    float* ctx_out  = out;                             // [B,S,DM]
    float* attn_out = out + (size_t)B_ * S_ * DM_;     // [B,H,S,S]

    void *pQ, *pK, *pV, *pC;
    cudaGetSymbolAddress(&pQ, g_Qh);
    cudaGetSymbolAddress(&pK, g_Kh);
    cudaGetSymbolAddress(&pV, g_Vh);
    cudaGetSymbolAddress(&pC, g_Ctx);

    const int smemAttn = SM_WORDS * 4;       // 174592
    const int smemProj = 2 * PBUF * 4;       // 73728
    cudaFuncSetAttribute(attn_mma, cudaFuncAttributeMaxDynamicSharedMemorySize, smemAttn);
    cudaFuncSetAttribute(proj_mma, cudaFuncAttributeMaxDynamicSharedMemorySize, smemProj);

    pack_mask<<<(B_*S_*(S_/32))/8, 256>>>(mask);

    dim3 gproj(M_/128, DM_/128);
    proj_mma<<<gproj, 256, smemProj>>>(q, Wq, nullptr, (float*)pQ, 1);
    proj_mma<<<gproj, 256, smemProj>>>(k, Wk, nullptr, (float*)pK, 1);
    proj_mma<<<gproj, 256, smemProj>>>(v, Wv, nullptr, (float*)pV, 1);

    attn_mma<<<dim3(S_/128, B_*H_), 512, smemAttn>>>(attn_out);

    rescale<<<B_*H_*S_, 256>>>(attn_out);

    proj_mma<<<gproj, 256, smemProj>>>((const float*)pC, Wo, bo, ctx_out, 0);
}

// round 7
// speedup vs baseline: 1.0679x; 1.0679x over previous
#include <cuda_runtime.h>

#define B_  4
#define S_  2048
#define DM_ 1024
#define H_  16
#define DK_ 64
#define M_  (B_*S_)   // 8192 rows

// Scratch (allocation-free rule: __device__ globals)
__device__ float g_Qh[(size_t)B_*H_*S_*DK_];
__device__ float g_Kh[(size_t)B_*H_*S_*DK_];
__device__ float g_Vh[(size_t)B_*H_*S_*DK_];
__device__ float g_Ctx[(size_t)M_*DM_];
__device__ float g_invl[(size_t)B_*H_*S_];
__device__ unsigned g_mbits[(size_t)B_*S_*(S_/32)];   // packed mask bits

// ---------------------------------------------------------------------------
// helpers
// ---------------------------------------------------------------------------
__device__ __forceinline__ unsigned f2tf(float x) {
    unsigned u;
    asm("cvt.rna.tf32.f32 %0, %1;" : "=r"(u) : "f"(x));
    return u;
}
__device__ __forceinline__ void mma_tf32(float c[4],
                                         unsigned a0, unsigned a1, unsigned a2, unsigned a3,
                                         unsigned b0, unsigned b1) {
    asm("mma.sync.aligned.m16n8k8.row.col.f32.tf32.tf32.f32 "
        "{%0,%1,%2,%3},{%4,%5,%6,%7},{%8,%9},{%0,%1,%2,%3};"
        : "+f"(c[0]), "+f"(c[1]), "+f"(c[2]), "+f"(c[3])
        : "r"(a0), "r"(a1), "r"(a2), "r"(a3), "r"(b0), "r"(b1));
}
__device__ __forceinline__ unsigned sm_u32(const void* p) {
    return (unsigned)__cvta_generic_to_shared(p);
}
__device__ __forceinline__ void ldsm4(unsigned r[4], unsigned addr) {
    asm volatile("ldmatrix.sync.aligned.m8n8.x4.shared.b16 {%0,%1,%2,%3}, [%4];"
        : "=r"(r[0]), "=r"(r[1]), "=r"(r[2]), "=r"(r[3]) : "r"(addr));
}
__device__ __forceinline__ void cp16(unsigned dst, const void* src) {
    asm volatile("cp.async.cg.shared.global [%0], [%1], 16;" :: "r"(dst), "l"(src));
}
__device__ __forceinline__ void cp_commit_wait() {
    asm volatile("cp.async.commit_group;");
    asm volatile("cp.async.wait_group 0;" ::: "memory");
}

// ---------------------------------------------------------------------------
// Pack mask into bits: g_mbits[b][row][w] bit j = (mask[b][row][32w+j] != 0)
// ---------------------------------------------------------------------------
__global__ __launch_bounds__(256) void pack_mask(const int* __restrict__ mask)
{
    const int lane = threadIdx.x & 31;
    const int gw = blockIdx.x * 8 + (threadIdx.x >> 5);   // global word index
    int m = mask[(size_t)gw * 32 + lane];
    unsigned bits = __ballot_sync(0xffffffffu, m != 0);
    if (lane == 0) g_mbits[gw] = bits;
}

// ---------------------------------------------------------------------------
// Projection GEMM (tf32 mma + ldmatrix): Y = X @ W^T (+bias).
// CTA tile 128m x 256n, BK=16, 8 warps 2(m)x4(n); warp = 64m x 64n.
// 32 mma per 8 ldsm4 per k-chunk (2x better feed ratio than 64x32 warps).
// ---------------------------------------------------------------------------
#define XSTR2 20
__global__ __launch_bounds__(256) void proj_mma(const float* __restrict__ X,
                                                const float* __restrict__ W,
                                                const float* __restrict__ bias,
                                                float* __restrict__ Y,
                                                int headsMode)
{
    __shared__ unsigned Xs[128 * XSTR2];   // [m][k], stride 20
    __shared__ unsigned Ws[256 * XSTR2];   // [n][k], stride 20
    const int tid = threadIdx.x;
    const int lane = tid & 31, wid = tid >> 5;
    const int wm = wid >> 2, wn = wid & 3;
    const int gr = lane >> 2, tg = lane & 3;
    const int m0 = blockIdx.x * 128, n0 = blockIdx.y * 256;

    const int arow = lane & 15;
    const int acol = ((lane >> 4) & 1) * 4;
    const int brow = ((lane >> 4) & 1) * 8 + (lane & 7);
    const int bcol = ((lane >> 3) & 1) * 4;
    const unsigned abase = sm_u32(Xs + (wm*64 + arow)*XSTR2 + acol);
    const unsigned bbase = sm_u32(Ws + (wn*64 + brow)*XSTR2 + bcol);

    const int lr = tid >> 1;          // 0..127
    const int lc = (tid & 1) * 8;     // k-col half (8 floats)

    float c[4][8][4];
    #pragma unroll
    for (int mi = 0; mi < 4; mi++)
        #pragma unroll
        for (int ni = 0; ni < 8; ni++)
            #pragma unroll
            for (int r = 0; r < 4; r++) c[mi][ni][r] = 0.f;

    const float* Xp = X + (size_t)(m0 + lr) * DM_ + lc;
    const float* Wp0 = W + (size_t)(n0 + lr) * DM_ + lc;
    const float* Wp1 = W + (size_t)(n0 + 128 + lr) * DM_ + lc;

    float4 px[2], pw[4];
    px[0] = *(const float4*)(Xp);  px[1] = *(const float4*)(Xp + 4);
    pw[0] = *(const float4*)(Wp0); pw[1] = *(const float4*)(Wp0 + 4);
    pw[2] = *(const float4*)(Wp1); pw[3] = *(const float4*)(Wp1 + 4);

    #pragma unroll 1
    for (int it = 0; it < DM_/16; it++) {
        *(uint4*)&Xs[lr*XSTR2 + lc]           = make_uint4(f2tf(px[0].x), f2tf(px[0].y), f2tf(px[0].z), f2tf(px[0].w));
        *(uint4*)&Xs[lr*XSTR2 + lc + 4]       = make_uint4(f2tf(px[1].x), f2tf(px[1].y), f2tf(px[1].z), f2tf(px[1].w));
        *(uint4*)&Ws[lr*XSTR2 + lc]           = make_uint4(f2tf(pw[0].x), f2tf(pw[0].y), f2tf(pw[0].z), f2tf(pw[0].w));
        *(uint4*)&Ws[lr*XSTR2 + lc + 4]       = make_uint4(f2tf(pw[1].x), f2tf(pw[1].y), f2tf(pw[1].z), f2tf(pw[1].w));
        *(uint4*)&Ws[(128+lr)*XSTR2 + lc]     = make_uint4(f2tf(pw[2].x), f2tf(pw[2].y), f2tf(pw[2].z), f2tf(pw[2].w));
        *(uint4*)&Ws[(128+lr)*XSTR2 + lc + 4] = make_uint4(f2tf(pw[3].x), f2tf(pw[3].y), f2tf(pw[3].z), f2tf(pw[3].w));
        __syncthreads();

        if (it + 1 < DM_/16) {
            const int ko = (it + 1) * 16;
            px[0] = *(const float4*)(Xp + ko);      px[1] = *(const float4*)(Xp + ko + 4);
            pw[0] = *(const float4*)(Wp0 + ko);     pw[1] = *(const float4*)(Wp0 + ko + 4);
            pw[2] = *(const float4*)(Wp1 + ko);     pw[3] = *(const float4*)(Wp1 + ko + 4);
        }

        #pragma unroll
        for (int kc = 0; kc < 2; kc++) {
            unsigned a[4][4], bb[8][2];
            #pragma unroll
            for (int mi = 0; mi < 4; mi++)
                ldsm4(a[mi], abase + (unsigned)(mi*16*XSTR2 + kc*8) * 4u);
            #pragma unroll
            for (int np = 0; np < 4; np++) {
                unsigned t[4];
                ldsm4(t, bbase + (unsigned)(np*16*XSTR2 + kc*8) * 4u);
                bb[2*np][0] = t[0]; bb[2*np][1] = t[1];
                bb[2*np+1][0] = t[2]; bb[2*np+1][1] = t[3];
            }
            #pragma unroll
            for (int mi = 0; mi < 4; mi++)
                #pragma unroll
                for (int ni = 0; ni < 8; ni++)
                    mma_tf32(c[mi][ni], a[mi][0], a[mi][1], a[mi][2], a[mi][3],
                             bb[ni][0], bb[ni][1]);
        }
        __syncthreads();
    }

    if (headsMode) {
        const int h = blockIdx.y*4 + wn;      // warp n-range is exactly one head
        #pragma unroll
        for (int mi = 0; mi < 4; mi++) {
            int m = m0 + wm*64 + mi*16 + gr;
            int b = m >> 11, s = m & (S_ - 1);
            size_t base0 = (((size_t)(b*H_ + h) * S_) + s) * DK_;
            #pragma unroll
            for (int ni = 0; ni < 8; ni++) {
                int dk = ni*8 + 2*tg;
                *(float2*)&Y[base0 + dk]          = make_float2(c[mi][ni][0], c[mi][ni][1]);
                *(float2*)&Y[base0 + 8*DK_ + dk]  = make_float2(c[mi][ni][2], c[mi][ni][3]);
            }
        }
    } else {
        #pragma unroll
        for (int mi = 0; mi < 4; mi++) {
            int m = m0 + wm*64 + mi*16 + gr;
            #pragma unroll
            for (int ni = 0; ni < 8; ni++) {
                int n = n0 + wn*64 + ni*8 + 2*tg;
                float b0 = bias[n], b1 = bias[n+1];
                *(float2*)&Y[(size_t)m * DM_ + n] =
                    make_float2(c[mi][ni][0] + b0, c[mi][ni][1] + b1);
                *(float2*)&Y[(size_t)(m+8) * DM_ + n] =
                    make_float2(c[mi][ni][2] + b0, c[mi][ni][3] + b1);
            }
        }
    }
}

// ---------------------------------------------------------------------------
// Fused attention, 512 threads / 16 warps (R5 structure).
// K,V tiles loaded via cp.async (raw fp32 -> tf32 truncation in mma).
// Scores: warps 4x4, warp 32q x 32k. PV: warps 4x4, warp 32q x 16d.
// smem words: Qs 128*68 | Ks 128*68 | Vs 128*72 | Ps 128*132 | rowSum 128
// ---------------------------------------------------------------------------
#define QSTR 68
#define VSTR 72
#define PSTR2 132
#define OFF_KS 8704
#define OFF_VS 17408
#define OFF_PS 26624
#define OFF_RS 43520
#define SM_WORDS 43648

__global__ __launch_bounds__(512) void attn_mma(float* __restrict__ attn)
{
    extern __shared__ unsigned smu[];
    unsigned* Qs = smu;
    unsigned* Ks = smu + OFF_KS;
    unsigned* Vs = smu + OFF_VS;   // natural [key][d], stride 72
    unsigned* Ps = smu + OFF_PS;
    float* rowSum = (float*)(smu + OFF_RS);

    const int tid = threadIdx.x;
    const int lane = tid & 31, wid = tid >> 5;
    const int wm = wid >> 2, wn = wid & 3;       // score map: 32q x 32k
    const int wm2 = wid & 3, wn2 = wid >> 2;     // PV map:    32q x 16d
    const int gr = lane >> 2, tg = lane & 3;
    const int qt = blockIdx.x, bh = blockIdx.y;
    const int b = bh >> 4, h = bh & 15;

    const int arow = lane & 15;
    const int acol = ((lane >> 4) & 1) * 4;
    const int brow = ((lane >> 4) & 1) * 8 + (lane & 7);
    const int bcol = ((lane >> 3) & 1) * 4;
    const unsigned qbase = sm_u32(Qs + (wm*32 + arow)*QSTR + acol);
    const unsigned kbase = sm_u32(Ks + (wn*32 + brow)*QSTR + bcol);
    const unsigned pbase = sm_u32(Ps + (wm2*32 + arow)*PSTR2 + acol);

    const float* Qb = g_Qh + ((size_t)bh * S_ + qt*128) * DK_;
    const float* Kb = g_Kh + (size_t)bh * S_ * DK_;
    const float* Vb = g_Vh + (size_t)bh * S_ * DK_;
    const unsigned* mbp = g_mbits + ((size_t)b * S_ + qt*128) * (S_/32);
    float* ab = attn + (size_t)bh * S_ * S_ + (size_t)qt * 128 * S_;

    if (tid < 128) rowSum[tid] = 0.f;

    const int lr = tid >> 2;            // 0..127
    const int seg = (tid & 3) * 16;     // d quarter
    const unsigned ksts = sm_u32(Ks + lr*QSTR + seg);
    const unsigned vsts = sm_u32(Vs + lr*VSTR + seg);
    { // Q load: scale by 1/sqrt(64), tf32 round (RNA)
        const float* qp = Qb + (size_t)lr * DK_ + seg;
        #pragma unroll
        for (int j = 0; j < 4; j++) {
            float4 v = *(const float4*)(qp + 4*j);
            *(uint4*)&Qs[lr*QSTR + seg + 4*j] =
                make_uint4(f2tf(v.x*0.125f), f2tf(v.y*0.125f),
                           f2tf(v.z*0.125f), f2tf(v.w*0.125f));
        }
    }

    float lacc[4];
    #pragma unroll
    for (int i = 0; i < 4; i++) lacc[i] = 0.f;
    float cacc[2][2][4];
    #pragma unroll
    for (int mi = 0; mi < 2; mi++)
        #pragma unroll
        for (int f = 0; f < 2; f++)
            #pragma unroll
            for (int r = 0; r < 4; r++) cacc[mi][f][r] = 0.f;

    for (int kt = 0; kt < 16; kt++) {
        __syncthreads();   // prev PV done with Vs/Ps; first iter: Qs/rowSum ready
        { // K, V tiles via cp.async (raw fp32; mma will truncate to tf32)
            const float* kp = Kb + (size_t)(kt*128 + lr) * DK_ + seg;
            const float* vp = Vb + (size_t)(kt*128 + lr) * DK_ + seg;
            #pragma unroll
            for (int j = 0; j < 4; j++) {
                cp16(ksts + 16u*j, kp + 4*j);
                cp16(vsts + 16u*j, vp + 4*j);
            }
        }
        // mask word prefetch (bits for this warp's 32-key window)
        unsigned mw[2][2];
        #pragma unroll
        for (int mi = 0; mi < 2; mi++) {
            const int r0 = wm*32 + mi*16 + gr;
            mw[mi][0] = mbp[(size_t)r0      * (S_/32) + kt*4 + wn];
            mw[mi][1] = mbp[(size_t)(r0+8)  * (S_/32) + kt*4 + wn];
        }
        cp_commit_wait();
        __syncthreads();

        // ---- scores: warp tile 32q x 32k, k-dim = 64 ----
        float sc[2][4][4];
        #pragma unroll
        for (int mi = 0; mi < 2; mi++)
            #pragma unroll
            for (int ni = 0; ni < 4; ni++)
                #pragma unroll
                for (int r = 0; r < 4; r++) sc[mi][ni][r] = 0.f;

        #pragma unroll
        for (int kc = 0; kc < 8; kc++) {
            unsigned a[2][4], bb[4][2];
            #pragma unroll
            for (int mi = 0; mi < 2; mi++)
                ldsm4(a[mi], qbase + (unsigned)(mi*16*QSTR + kc*8) * 4u);
            #pragma unroll
            for (int np = 0; np < 2; np++) {
                unsigned t[4];
                ldsm4(t, kbase + (unsigned)(np*16*QSTR + kc*8) * 4u);
                bb[2*np][0] = t[0]; bb[2*np][1] = t[1];
                bb[2*np+1][0] = t[2]; bb[2*np+1][1] = t[3];
            }
            #pragma unroll
            for (int mi = 0; mi < 2; mi++)
                #pragma unroll
                for (int ni = 0; ni < 4; ni++)
                    mma_tf32(sc[mi][ni], a[mi][0], a[mi][1], a[mi][2], a[mi][3],
                             bb[ni][0], bb[ni][1]);
        }

        // ---- mask(bits) + exp; unnormalized probs -> global(fp32) + Ps(tf32) ----
        #pragma unroll
        for (int mi = 0; mi < 2; mi++) {
            const int r0 = wm*32 + mi*16 + gr;
            #pragma unroll
            for (int ni = 0; ni < 4; ni++) {
                const int ck = wn*32 + ni*8 + 2*tg;
                const int bit = ni*8 + 2*tg;
                const size_t gcol = (size_t)kt*128 + ck;
                float p00 = (mw[mi][0] >> bit     & 1u) ? __expf(sc[mi][ni][0]) : 0.f;
                float p01 = (mw[mi][0] >> (bit+1) & 1u) ? __expf(sc[mi][ni][1]) : 0.f;
                float p10 = (mw[mi][1] >> bit     & 1u) ? __expf(sc[mi][ni][2]) : 0.f;
                float p11 = (mw[mi][1] >> (bit+1) & 1u) ? __expf(sc[mi][ni][3]) : 0.f;
                lacc[mi*2]   += p00 + p01;
                lacc[mi*2+1] += p10 + p11;
                *(float2*)&ab[(size_t)r0     * S_ + gcol] = make_float2(p00, p01);
                *(float2*)&ab[(size_t)(r0+8) * S_ + gcol] = make_float2(p10, p11);
                *(uint2*)&Ps[r0    *PSTR2 + ck] = make_uint2(f2tf(p00), f2tf(p01));
                *(uint2*)&Ps[(r0+8)*PSTR2 + ck] = make_uint2(f2tf(p10), f2tf(p11));
            }
        }
        __syncthreads();

        // ---- PV: warp tile 32q x 16d, k-dim = 128 keys ----
        #pragma unroll
        for (int kc = 0; kc < 16; kc++) {
            unsigned a2[2][4];
            ldsm4(a2[0], pbase + (unsigned)(kc*8) * 4u);
            ldsm4(a2[1], pbase + (unsigned)(16*PSTR2 + kc*8) * 4u);
            unsigned vb[2][2];
            #pragma unroll
            for (int f = 0; f < 2; f++) {
                const int d = wn2*16 + f*8 + gr;
                vb[f][0] = Vs[(kc*8 + tg    )*VSTR + d];
                vb[f][1] = Vs[(kc*8 + tg + 4)*VSTR + d];
            }
            #pragma unroll
            for (int mi = 0; mi < 2; mi++)
                #pragma unroll
                for (int f = 0; f < 2; f++)
                    mma_tf32(cacc[mi][f], a2[mi][0], a2[mi][1], a2[mi][2], a2[mi][3],
                             vb[f][0], vb[f][1]);
        }
    }

    // ---- row sums: quad shuffle reduce + cross-warp atomic ----
    #pragma unroll
    for (int i = 0; i < 4; i++) {
        float v = lacc[i];
        v += __shfl_xor_sync(0xffffffffu, v, 1);
        v += __shfl_xor_sync(0xffffffffu, v, 2);
        lacc[i] = v;
    }
    if (tg == 0) {
        #pragma unroll
        for (int mi = 0; mi < 2; mi++) {
            atomicAdd(&rowSum[wm*32 + mi*16 + gr],     lacc[mi*2]);
            atomicAdd(&rowSum[wm*32 + mi*16 + gr + 8], lacc[mi*2+1]);
        }
    }
    __syncthreads();
    if (tid < 128)
        g_invl[(size_t)bh * S_ + qt*128 + tid] = 1.0f / rowSum[tid];

    // ---- context write (scaled by 1/l), permuted to [b][s][h*64+d] ----
    #pragma unroll
    for (int mi = 0; mi < 2; mi++) {
        const int r0 = wm2*32 + mi*16 + gr;
        const float s0 = 1.0f / rowSum[r0];
        const float s1 = 1.0f / rowSum[r0 + 8];
        #pragma unroll
        for (int f = 0; f < 2; f++) {
            const int d = wn2*16 + f*8 + 2*tg;
            size_t d0 = ((size_t)(b*S_ + qt*128 + r0    )) * DM_ + h*DK_ + d;
            size_t d1 = ((size_t)(b*S_ + qt*128 + r0 + 8)) * DM_ + h*DK_ + d;
            *(float2*)&g_Ctx[d0] = make_float2(cacc[mi][f][0]*s0, cacc[mi][f][1]*s0);
            *(float2*)&g_Ctx[d1] = make_float2(cacc[mi][f][2]*s1, cacc[mi][f][3]*s1);
        }
    }
}

// ---------------------------------------------------------------------------
// Normalize attention rows: attn[row][:] *= invl[row]
// ---------------------------------------------------------------------------
__global__ __launch_bounds__(256) void rescale(float* __restrict__ attn)
{
    const int row = blockIdx.x;
    const float s = g_invl[row];
    float4* p = (float4*)(attn + (size_t)row * S_);
    const int t = threadIdx.x;
    float4 v0 = p[t], v1 = p[t + 256];
    v0.x *= s; v0.y *= s; v0.z *= s; v0.w *= s;
    v1.x *= s; v1.y *= s; v1.z *= s; v1.w *= s;
    p[t] = v0; p[t + 256] = v1;
}

// ---------------------------------------------------------------------------
extern "C" void kernel_launch(void* const* d_in, const int* in_sizes, int n_in,
                              void* d_out, int out_size)
{
    const float* q    = (const float*)d_in[0];
    const float* k    = (const float*)d_in[1];
    const float* v    = (const float*)d_in[2];
    const int*   mask = (const int*)  d_in[3];
    const float* Wq   = (const float*)d_in[4];
    const float* Wk   = (const float*)d_in[5];
    const float* Wv   = (const float*)d_in[6];
    const float* Wo   = (const float*)d_in[7];
    const float* bo   = (const float*)d_in[8];

    float* out      = (float*)d_out;
    float* ctx_out  = out;                             // [B,S,DM]
    float* attn_out = out + (size_t)B_ * S_ * DM_;     // [B,H,S,S]

    void *pQ, *pK, *pV, *pC;
    cudaGetSymbolAddress(&pQ, g_Qh);
    cudaGetSymbolAddress(&pK, g_Kh);
    cudaGetSymbolAddress(&pV, g_Vh);
    cudaGetSymbolAddress(&pC, g_Ctx);

    const int smemAttn = SM_WORDS * 4;   // 174592
    cudaFuncSetAttribute(attn_mma, cudaFuncAttributeMaxDynamicSharedMemorySize, smemAttn);

    pack_mask<<<(B_*S_*(S_/32))/8, 256>>>(mask);

    dim3 gproj(M_/128, DM_/256);
    proj_mma<<<gproj, 256>>>(q, Wq, nullptr, (float*)pQ, 1);
    proj_mma<<<gproj, 256>>>(k, Wk, nullptr, (float*)pK, 1);
    proj_mma<<<gproj, 256>>>(v, Wv, nullptr, (float*)pV, 1);

    attn_mma<<<dim3(S_/128, B_*H_), 512, smemAttn>>>(attn_out);

    rescale<<<B_*H_*S_, 256>>>(attn_out);

    proj_mma<<<gproj, 256>>>((const float*)pC, Wo, bo, ctx_out, 0);
}

// round 10
// speedup vs baseline: 1.1140x; 1.0432x over previous
#include <cuda_runtime.h>

#define B_  4
#define S_  2048
#define DM_ 1024
#define H_  16
#define DK_ 64
#define M_  (B_*S_)   // 8192 rows

// Scratch (allocation-free rule: __device__ globals)
__device__ float g_Qh[(size_t)B_*H_*S_*DK_];
__device__ float g_Kh[(size_t)B_*H_*S_*DK_];
__device__ float g_Vh[(size_t)B_*H_*S_*DK_];
__device__ float g_Ctx[(size_t)M_*DM_];
__device__ float g_invl[(size_t)B_*H_*S_];
__device__ unsigned g_mbits[(size_t)B_*S_*(S_/32)];   // packed mask bits

// ---------------------------------------------------------------------------
// helpers
// ---------------------------------------------------------------------------
__device__ __forceinline__ unsigned f2tf(float x) {
    unsigned u;
    asm("cvt.rna.tf32.f32 %0, %1;" : "=r"(u) : "f"(x));
    return u;
}
__device__ __forceinline__ void mma_tf32(float c[4],
                                         unsigned a0, unsigned a1, unsigned a2, unsigned a3,
                                         unsigned b0, unsigned b1) {
    asm("mma.sync.aligned.m16n8k8.row.col.f32.tf32.tf32.f32 "
        "{%0,%1,%2,%3},{%4,%5,%6,%7},{%8,%9},{%0,%1,%2,%3};"
        : "+f"(c[0]), "+f"(c[1]), "+f"(c[2]), "+f"(c[3])
        : "r"(a0), "r"(a1), "r"(a2), "r"(a3), "r"(b0), "r"(b1));
}
__device__ __forceinline__ unsigned sm_u32(const void* p) {
    return (unsigned)__cvta_generic_to_shared(p);
}
__device__ __forceinline__ void ldsm4(unsigned r[4], unsigned addr) {
    asm volatile("ldmatrix.sync.aligned.m8n8.x4.shared.b16 {%0,%1,%2,%3}, [%4];"
        : "=r"(r[0]), "=r"(r[1]), "=r"(r[2]), "=r"(r[3]) : "r"(addr));
}
__device__ __forceinline__ void cp16(unsigned dst, const void* src) {
    asm volatile("cp.async.cg.shared.global [%0], [%1], 16;" :: "r"(dst), "l"(src));
}
__device__ __forceinline__ void cp_commit_wait() {
    asm volatile("cp.async.commit_group;");
    asm volatile("cp.async.wait_group 0;" ::: "memory");
}

// ---------------------------------------------------------------------------
// Fused projection GEMM + optional aux memory work in extra blocks.
// Proj (bid < 512): 128x128 tile, BK=32, 8 warps 2(m)x4(n), warp 64m x 32n
// (~124 regs, 2 CTAs/SM). Aux (bid >= 512), 2048 aux blocks:
//   auxMode 1: pack mask bits (block packs 256 words; 2048*256 = all words)
//   auxMode 2: rescale 64 attention rows by g_invl (2048*64 = all 131072 rows)
// ---------------------------------------------------------------------------
#define XSTR 36
__global__ __launch_bounds__(256) void proj_fused(const float* __restrict__ X,
                                                  const float* __restrict__ W,
                                                  const float* __restrict__ bias,
                                                  float* __restrict__ Y,
                                                  int headsMode, int auxMode,
                                                  const int* __restrict__ mask,
                                                  float* __restrict__ attnRS)
{
    const int bid = blockIdx.x;
    if (bid >= 512) {
        const int aux = bid - 512;
        if (auxMode == 1) {            // ---- pack mask bits ----
            const int lane = threadIdx.x & 31, w = threadIdx.x >> 5;
            size_t base = (size_t)aux * 256 + (size_t)w * 32;
            #pragma unroll 4
            for (int i = 0; i < 32; i++) {
                int m = mask[(base + i) * 32 + lane];
                unsigned bits = __ballot_sync(0xffffffffu, m != 0);
                if (lane == 0) g_mbits[base + i] = bits;
            }
        } else {                       // ---- rescale 64 attention rows ----
            const int t = threadIdx.x;
            #pragma unroll 4
            for (int r = 0; r < 64; r++) {
                const int row = aux * 64 + r;
                const float s = g_invl[row];
                float4* p = (float4*)(attnRS + (size_t)row * S_);
                float4 v0 = p[t], v1 = p[t + 256];
                v0.x *= s; v0.y *= s; v0.z *= s; v0.w *= s;
                v1.x *= s; v1.y *= s; v1.z *= s; v1.w *= s;
                p[t] = v0; p[t + 256] = v1;
            }
        }
        return;
    }

    __shared__ unsigned Xs[128 * XSTR];
    __shared__ unsigned Ws[128 * XSTR];
    const int tid = threadIdx.x;
    const int lane = tid & 31, wid = tid >> 5;
    const int wm = wid >> 2, wn = wid & 3;
    const int gr = lane >> 2, tg = lane & 3;
    const int m0 = (bid & 63) * 128, n0 = (bid >> 6) * 128;

    const int arow = lane & 15;
    const int acol = ((lane >> 4) & 1) * 4;
    const int brow = ((lane >> 4) & 1) * 8 + (lane & 7);
    const int bcol = ((lane >> 3) & 1) * 4;
    const unsigned abase = sm_u32(Xs + (wm*64 + arow)*XSTR + acol);
    const unsigned bbase = sm_u32(Ws + (wn*32 + brow)*XSTR + bcol);

    const int lr = tid >> 1;          // 0..127 (row)
    const int lh = (tid & 1) * 16;    // k-half

    float c[4][4][4];
    #pragma unroll
    for (int mi = 0; mi < 4; mi++)
        #pragma unroll
        for (int ni = 0; ni < 4; ni++)
            #pragma unroll
            for (int r = 0; r < 4; r++) c[mi][ni][r] = 0.f;

    const float* Xp = X + (size_t)(m0 + lr) * DM_ + lh;
    const float* Wp = W + (size_t)(n0 + lr) * DM_ + lh;

    float4 px[4], pw[4];
    #pragma unroll
    for (int j = 0; j < 4; j++) { px[j] = *(const float4*)(Xp + 4*j); pw[j] = *(const float4*)(Wp + 4*j); }

    #pragma unroll 1
    for (int it = 0; it < 32; it++) {
        #pragma unroll
        for (int j = 0; j < 4; j++) {
            *(uint4*)&Xs[lr*XSTR + lh + 4*j] = make_uint4(f2tf(px[j].x), f2tf(px[j].y), f2tf(px[j].z), f2tf(px[j].w));
            *(uint4*)&Ws[lr*XSTR + lh + 4*j] = make_uint4(f2tf(pw[j].x), f2tf(pw[j].y), f2tf(pw[j].z), f2tf(pw[j].w));
        }
        __syncthreads();

        if (it + 1 < 32) {
            const int ko = (it + 1) * 32;
            #pragma unroll
            for (int j = 0; j < 4; j++) { px[j] = *(const float4*)(Xp + ko + 4*j); pw[j] = *(const float4*)(Wp + ko + 4*j); }
        }

        #pragma unroll
        for (int kc = 0; kc < 4; kc++) {
            unsigned a[4][4], bb[4][2];
            #pragma unroll
            for (int mi = 0; mi < 4; mi++)
                ldsm4(a[mi], abase + (unsigned)(mi*16*XSTR + kc*8) * 4u);
            #pragma unroll
            for (int np = 0; np < 2; np++) {
                unsigned t[4];
                ldsm4(t, bbase + (unsigned)(np*16*XSTR + kc*8) * 4u);
                bb[2*np][0] = t[0]; bb[2*np][1] = t[1];
                bb[2*np+1][0] = t[2]; bb[2*np+1][1] = t[3];
            }
            #pragma unroll
            for (int mi = 0; mi < 4; mi++)
                #pragma unroll
                for (int ni = 0; ni < 4; ni++)
                    mma_tf32(c[mi][ni], a[mi][0], a[mi][1], a[mi][2], a[mi][3],
                             bb[ni][0], bb[ni][1]);
        }
        __syncthreads();
    }

    if (headsMode) {
        #pragma unroll
        for (int mi = 0; mi < 4; mi++) {
            int m = m0 + wm*64 + mi*16 + gr;
            int b = m >> 11, s = m & (S_ - 1);
            #pragma unroll
            for (int ni = 0; ni < 4; ni++) {
                int n = n0 + wn*32 + ni*8 + 2*tg;
                int h = n >> 6, dk = n & 63;
                size_t base = (((size_t)(b*H_ + h) * S_) + s) * DK_ + dk;
                *(float2*)&Y[base]         = make_float2(c[mi][ni][0], c[mi][ni][1]);
                *(float2*)&Y[base + 8*DK_] = make_float2(c[mi][ni][2], c[mi][ni][3]);
            }
        }
    } else {
        #pragma unroll
        for (int mi = 0; mi < 4; mi++) {
            int m = m0 + wm*64 + mi*16 + gr;
            #pragma unroll
            for (int ni = 0; ni < 4; ni++) {
                int n = n0 + wn*32 + ni*8 + 2*tg;
                float b0 = bias[n], b1 = bias[n+1];
                *(float2*)&Y[(size_t)m * DM_ + n] =
                    make_float2(c[mi][ni][0] + b0, c[mi][ni][1] + b1);
                *(float2*)&Y[(size_t)(m+8) * DM_ + n] =
                    make_float2(c[mi][ni][2] + b0, c[mi][ni][3] + b1);
            }
        }
    }
}

// ---------------------------------------------------------------------------
// Fused attention, 512 threads / 16 warps (R7 structure, tf32 throughout).
// K,V tiles loaded via cp.async (raw fp32 -> tf32 truncation in mma).
// Scores: warps 4x4, warp 32q x 32k. PV: warps 4x4, warp 32q x 16d.
// smem words: Qs 128*68 | Ks 128*68 | Vs 128*72 | Ps 128*132 | rowSum 128
// ---------------------------------------------------------------------------
#define QSTR 68
#define VSTR 72
#define PSTR2 132
#define OFF_KS 8704
#define OFF_VS 17408
#define OFF_PS 26624
#define OFF_RS 43520
#define SM_WORDS 43648

__global__ __launch_bounds__(512) void attn_mma(float* __restrict__ attn)
{
    extern __shared__ unsigned smu[];
    unsigned* Qs = smu;
    unsigned* Ks = smu + OFF_KS;
    unsigned* Vs = smu + OFF_VS;   // natural [key][d], stride 72
    unsigned* Ps = smu + OFF_PS;
    float* rowSum = (float*)(smu + OFF_RS);

    const int tid = threadIdx.x;
    const int lane = tid & 31, wid = tid >> 5;
    const int wm = wid >> 2, wn = wid & 3;       // score map: 32q x 32k
    const int wm2 = wid & 3, wn2 = wid >> 2;     // PV map:    32q x 16d
    const int gr = lane >> 2, tg = lane & 3;
    const int qt = blockIdx.x, bh = blockIdx.y;
    const int b = bh >> 4, h = bh & 15;

    const int arow = lane & 15;
    const int acol = ((lane >> 4) & 1) * 4;
    const int brow = ((lane >> 4) & 1) * 8 + (lane & 7);
    const int bcol = ((lane >> 3) & 1) * 4;
    const unsigned qbase = sm_u32(Qs + (wm*32 + arow)*QSTR + acol);
    const unsigned kbase = sm_u32(Ks + (wn*32 + brow)*QSTR + bcol);
    const unsigned pbase = sm_u32(Ps + (wm2*32 + arow)*PSTR2 + acol);

    const float* Qb = g_Qh + ((size_t)bh * S_ + qt*128) * DK_;
    const float* Kb = g_Kh + (size_t)bh * S_ * DK_;
    const float* Vb = g_Vh + (size_t)bh * S_ * DK_;
    const unsigned* mbp = g_mbits + ((size_t)b * S_ + qt*128) * (S_/32);
    float* ab = attn + (size_t)bh * S_ * S_ + (size_t)qt * 128 * S_;

    if (tid < 128) rowSum[tid] = 0.f;

    const int lr = tid >> 2;            // 0..127
    const int seg = (tid & 3) * 16;     // d quarter
    const unsigned ksts = sm_u32(Ks + lr*QSTR + seg);
    const unsigned vsts = sm_u32(Vs + lr*VSTR + seg);
    { // Q load: scale by 1/sqrt(64), tf32 round (RNA)
        const float* qp = Qb + (size_t)lr * DK_ + seg;
        #pragma unroll
        for (int j = 0; j < 4; j++) {
            float4 v = *(const float4*)(qp + 4*j);
            *(uint4*)&Qs[lr*QSTR + seg + 4*j] =
                make_uint4(f2tf(v.x*0.125f), f2tf(v.y*0.125f),
                           f2tf(v.z*0.125f), f2tf(v.w*0.125f));
        }
    }

    float lacc[4];
    #pragma unroll
    for (int i = 0; i < 4; i++) lacc[i] = 0.f;
    float cacc[2][2][4];
    #pragma unroll
    for (int mi = 0; mi < 2; mi++)
        #pragma unroll
        for (int f = 0; f < 2; f++)
            #pragma unroll
            for (int r = 0; r < 4; r++) cacc[mi][f][r] = 0.f;

    for (int kt = 0; kt < 16; kt++) {
        __syncthreads();   // prev PV done with Vs/Ps; first iter: Qs/rowSum ready
        { // K, V tiles via cp.async (raw fp32; mma will truncate to tf32)
            const float* kp = Kb + (size_t)(kt*128 + lr) * DK_ + seg;
            const float* vp = Vb + (size_t)(kt*128 + lr) * DK_ + seg;
            #pragma unroll
            for (int j = 0; j < 4; j++) {
                cp16(ksts + 16u*j, kp + 4*j);
                cp16(vsts + 16u*j, vp + 4*j);
            }
        }
        // mask word prefetch (bits for this warp's 32-key window)
        unsigned mw[2][2];
        #pragma unroll
        for (int mi = 0; mi < 2; mi++) {
            const int r0 = wm*32 + mi*16 + gr;
            mw[mi][0] = mbp[(size_t)r0      * (S_/32) + kt*4 + wn];
            mw[mi][1] = mbp[(size_t)(r0+8)  * (S_/32) + kt*4 + wn];
        }
        cp_commit_wait();
        __syncthreads();

        // ---- scores: warp tile 32q x 32k, k-dim = 64 ----
        float sc[2][4][4];
        #pragma unroll
        for (int mi = 0; mi < 2; mi++)
            #pragma unroll
            for (int ni = 0; ni < 4; ni++)
                #pragma unroll
                for (int r = 0; r < 4; r++) sc[mi][ni][r] = 0.f;

        #pragma unroll
        for (int kc = 0; kc < 8; kc++) {
            unsigned a[2][4], bb[4][2];
            #pragma unroll
            for (int mi = 0; mi < 2; mi++)
                ldsm4(a[mi], qbase + (unsigned)(mi*16*QSTR + kc*8) * 4u);
            #pragma unroll
            for (int np = 0; np < 2; np++) {
                unsigned t[4];
                ldsm4(t, kbase + (unsigned)(np*16*QSTR + kc*8) * 4u);
                bb[2*np][0] = t[0]; bb[2*np][1] = t[1];
                bb[2*np+1][0] = t[2]; bb[2*np+1][1] = t[3];
            }
            #pragma unroll
            for (int mi = 0; mi < 2; mi++)
                #pragma unroll
                for (int ni = 0; ni < 4; ni++)
                    mma_tf32(sc[mi][ni], a[mi][0], a[mi][1], a[mi][2], a[mi][3],
                             bb[ni][0], bb[ni][1]);
        }

        // ---- mask(bits) + exp; unnormalized probs -> global(fp32) + Ps(tf32) ----
        #pragma unroll
        for (int mi = 0; mi < 2; mi++) {
            const int r0 = wm*32 + mi*16 + gr;
            #pragma unroll
            for (int ni = 0; ni < 4; ni++) {
                const int ck = wn*32 + ni*8 + 2*tg;
                const int bit = ni*8 + 2*tg;
                const size_t gcol = (size_t)kt*128 + ck;
                float p00 = (mw[mi][0] >> bit     & 1u) ? __expf(sc[mi][ni][0]) : 0.f;
                float p01 = (mw[mi][0] >> (bit+1) & 1u) ? __expf(sc[mi][ni][1]) : 0.f;
                float p10 = (mw[mi][1] >> bit     & 1u) ? __expf(sc[mi][ni][2]) : 0.f;
                float p11 = (mw[mi][1] >> (bit+1) & 1u) ? __expf(sc[mi][ni][3]) : 0.f;
                lacc[mi*2]   += p00 + p01;
                lacc[mi*2+1] += p10 + p11;
                *(float2*)&ab[(size_t)r0     * S_ + gcol] = make_float2(p00, p01);
                *(float2*)&ab[(size_t)(r0+8) * S_ + gcol] = make_float2(p10, p11);
                *(uint2*)&Ps[r0    *PSTR2 + ck] = make_uint2(f2tf(p00), f2tf(p01));
                *(uint2*)&Ps[(r0+8)*PSTR2 + ck] = make_uint2(f2tf(p10), f2tf(p11));
            }
        }
        __syncthreads();

        // ---- PV: warp tile 32q x 16d, k-dim = 128 keys ----
        #pragma unroll
        for (int kc = 0; kc < 16; kc++) {
            unsigned a2[2][4];
            ldsm4(a2[0], pbase + (unsigned)(kc*8) * 4u);
            ldsm4(a2[1], pbase + (unsigned)(16*PSTR2 + kc*8) * 4u);
            unsigned vb[2][2];
            #pragma unroll
            for (int f = 0; f < 2; f++) {
                const int d = wn2*16 + f*8 + gr;
                vb[f][0] = Vs[(kc*8 + tg    )*VSTR + d];
                vb[f][1] = Vs[(kc*8 + tg + 4)*VSTR + d];
            }
            #pragma unroll
            for (int mi = 0; mi < 2; mi++)
                #pragma unroll
                for (int f = 0; f < 2; f++)
                    mma_tf32(cacc[mi][f], a2[mi][0], a2[mi][1], a2[mi][2], a2[mi][3],
                             vb[f][0], vb[f][1]);
        }
    }

    // ---- row sums: quad shuffle reduce + cross-warp atomic ----
    #pragma unroll
    for (int i = 0; i < 4; i++) {
        float v = lacc[i];
        v += __shfl_xor_sync(0xffffffffu, v, 1);
        v += __shfl_xor_sync(0xffffffffu, v, 2);
        lacc[i] = v;
    }
    if (tg == 0) {
        #pragma unroll
        for (int mi = 0; mi < 2; mi++) {
            atomicAdd(&rowSum[wm*32 + mi*16 + gr],     lacc[mi*2]);
            atomicAdd(&rowSum[wm*32 + mi*16 + gr + 8], lacc[mi*2+1]);
        }
    }
    __syncthreads();
    if (tid < 128)
        g_invl[(size_t)bh * S_ + qt*128 + tid] = 1.0f / rowSum[tid];

    // ---- context write (scaled by 1/l), permuted to [b][s][h*64+d] ----
    #pragma unroll
    for (int mi = 0; mi < 2; mi++) {
        const int r0 = wm2*32 + mi*16 + gr;
        const float s0 = 1.0f / rowSum[r0];
        const float s1 = 1.0f / rowSum[r0 + 8];
        #pragma unroll
        for (int f = 0; f < 2; f++) {
            const int d = wn2*16 + f*8 + 2*tg;
            size_t d0 = ((size_t)(b*S_ + qt*128 + r0    )) * DM_ + h*DK_ + d;
            size_t d1 = ((size_t)(b*S_ + qt*128 + r0 + 8)) * DM_ + h*DK_ + d;
            *(float2*)&g_Ctx[d0] = make_float2(cacc[mi][f][0]*s0, cacc[mi][f][1]*s0);
            *(float2*)&g_Ctx[d1] = make_float2(cacc[mi][f][2]*s1, cacc[mi][f][3]*s1);
        }
    }
}

// ---------------------------------------------------------------------------
extern "C" void kernel_launch(void* const* d_in, const int* in_sizes, int n_in,
                              void* d_out, int out_size)
{
    const float* q    = (const float*)d_in[0];
    const float* k    = (const float*)d_in[1];
    const float* v    = (const float*)d_in[2];
    const int*   mask = (const int*)  d_in[3];
    const float* Wq   = (const float*)d_in[4];
    const float* Wk   = (const float*)d_in[5];
    const float* Wv   = (const float*)d_in[6];
    const float* Wo   = (const float*)d_in[7];
    const float* bo   = (const float*)d_in[8];

    float* out      = (float*)d_out;
    float* ctx_out  = out;                             // [B,S,DM]
    float* attn_out = out + (size_t)B_ * S_ * DM_;     // [B,H,S,S]

    void *pQ, *pK, *pV, *pC;
    cudaGetSymbolAddress(&pQ, g_Qh);
    cudaGetSymbolAddress(&pK, g_Kh);
    cudaGetSymbolAddress(&pV, g_Vh);
    cudaGetSymbolAddress(&pC, g_Ctx);

    const int smemAttn = SM_WORDS * 4;   // 174592
    cudaFuncSetAttribute(attn_mma, cudaFuncAttributeMaxDynamicSharedMemorySize, smemAttn);

    // Q projection + mask packing overlapped (512 proj blocks + 2048 pack blocks)
    proj_fused<<<512 + 2048, 256>>>(q, Wq, nullptr, (float*)pQ, 1, 1, mask, nullptr);
    proj_fused<<<512, 256>>>(k, Wk, nullptr, (float*)pK, 1, 0, nullptr, nullptr);
    proj_fused<<<512, 256>>>(v, Wv, nullptr, (float*)pV, 1, 0, nullptr, nullptr);

    attn_mma<<<dim3(S_/128, B_*H_), 512, smemAttn>>>(attn_out);

    // Output projection + attention rescale overlapped (512 + 2048 blocks)
    proj_fused<<<512 + 2048, 256>>>((const float*)pC, Wo, bo, ctx_out, 0, 2,
                                    nullptr, attn_out);
}